// round 10
// baseline (speedup 1.0000x reference)
#include <cuda_runtime.h>

// sLSTM, T=512, B=16, HID=1024, H=4 heads (D=256), G=4 gates.
// R10: R7 partition (128 CTAs = 4 heads x 32 channel-groups of 8), but the
// batch dim is split into two INDEPENDENT streams (b 0-7 = A, 8-15 = B),
// phase-interleaved inside each CTA so each stream's flag/L2/stage latency
// hides under the other stream's GEMM+elementwise. Fast-math gates,
// reduce-scatter shfl butterfly, W in registers, f32x2 FMA.

#define T_STEPS 512
#define BATCH   16
#define HID     1024
#define NCTA    128
#define TPB     256
#define RS      9      // sRaw row stride (8 batches + 1 pad)

__device__ unsigned g_flagA[NCTA];
__device__ unsigned g_flagB[NCTA];

__global__ void prep_kernel() {
    int i = threadIdx.x;
    if (i < NCTA) { g_flagA[i] = 0u; g_flagB[i] = 0u; }
}

__device__ __forceinline__ void ffma2(unsigned long long &acc,
                                      unsigned long long a,
                                      unsigned long long b) {
    asm("fma.rn.f32x2 %0, %1, %2, %0;" : "+l"(acc) : "l"(a), "l"(b));
}
__device__ __forceinline__ float fold2(unsigned long long a) {
    return __uint_as_float((unsigned)(a & 0xffffffffu)) +
           __uint_as_float((unsigned)(a >> 32));
}
__device__ __forceinline__ unsigned ld_acq(const unsigned* p) {
    unsigned v;
    asm volatile("ld.acquire.gpu.global.u32 %0, [%1];" : "=r"(v) : "l"(p));
    return v;
}
__device__ __forceinline__ void st_rel(unsigned* p, unsigned v) {
    asm volatile("st.release.gpu.global.u32 [%0], %1;" :: "l"(p), "r"(v) : "memory");
}

struct St { float h, c, n, m; };

// Fast-math gate update. lf uses log(sigmoid(f)) = min(f,0) - log(1+exp(-|f|)).
__device__ __forceinline__ float gate_update(St &s, float iraw, float fraw,
                                             float zraw, float oraw, int t) {
    float e   = __expf(-fabsf(fraw));
    float lf  = s.m + (fraw < 0.f ? fraw : 0.f) - __logf(1.f + e);
    float mn  = (t == 0) ? iraw : fmaxf(iraw, lf);
    float og  = __fdividef(1.f, 1.f + __expf(-oraw));
    float ig  = __expf(iraw - mn);
    float fg  = __expf(lf - mn);
    float t2  = __expf(2.f * zraw);                 // tanh(z) = 1 - 2/(1+e^{2z})
    float th  = 1.f - __fdividef(2.f, t2 + 1.f);
    float cn  = fg * s.c + ig * th;
    float nn  = fg * s.h + ig;                      // reference uses h here
    float hn  = __fdividef(og * cn, nn);
    s.c = cn; s.n = nn; s.m = mn; s.h = hn;
    return hn;
}

__global__ __launch_bounds__(TPB, 1) void slstm_kernel(
    const float* __restrict__ x,     // (512, 16, 4096)
    const float* __restrict__ rk,    // (4, 256, 4, 256)
    const float* __restrict__ bias,  // flat 4096
    float* __restrict__ out)         // outs (512,16,1024) ++ final (4,16,1024)
{
    // per-stream h tile: 8 batches x 64 float4 (k=256), stride 65, XOR swizzle
    __shared__ float4 sHA[8 * 65];
    __shared__ float4 sHB[8 * 65];
    __shared__ float  sRaw[32 * RS + 4];

    const int c     = blockIdx.x;
    const int head  = c >> 5;
    const int dd0   = (c & 31) << 3;    // 8 channels of this CTA
    const int hbase = head << 8;
    const int tid   = threadIdx.x;
    const int wq    = tid >> 5;         // warp: rows 4wq..4wq+3
    const int lane  = tid & 31;
    const int ks    = lane & 7;         // k-slice [32ks, 32ks+32)
    const int bt    = lane >> 3;        // batch pair {bt, bt+4} (stream-local)
    const int s0    = ks & 1, s1 = (ks >> 1) & 1, s2 = (ks >> 2) & 1;

    // ---- one-time W gather into registers (same verified formula as R7) ----
    float Wf[128];   // [(i*8+j)*4 + e], row=4wq+i, d = 32ks+4j+e
    #pragma unroll
    for (int i = 0; i < 4; ++i) {
        int row = 4 * wq + i;
        int g2  = row >> 3;
        int dd  = dd0 + (row & 7);
        int gx  = dd >> 6;
        int bbs = (dd & 63) << 2;
        #pragma unroll
        for (int j = 0; j < 8; ++j)
            #pragma unroll
            for (int e = 0; e < 4; ++e) {
                int d  = 32 * ks + 4 * j + e;
                int a  = ((d & 63) << 2) + g2;
                int bb = bbs + (d >> 6);
                Wf[(i * 8 + j) * 4 + e] = __ldg(&rk[((hbase + a) * 4 + gx) * 256 + bb]);
            }
    }
    const unsigned long long* W2 = (const unsigned long long*)Wf;

    // ---- elementwise role: tid<64 owns (channel ch, stream-local batch b) for BOTH streams
    const int ch  = tid >> 3;           // 0..7
    const int bel = tid & 7;            // 0..7
    const int q_u = hbase + dd0 + ch;
    float bias_g[4];
    #pragma unroll
    for (int g = 0; g < 4; ++g) bias_g[g] = bias[(g << 10) + q_u];
    St stA = {0.f, 0.f, 0.f, 0.f}, stB = {0.f, 0.f, 0.f, 0.f};

    // zero both h tiles (h_{-1} = 0)
    {
        float4 z = make_float4(0.f, 0.f, 0.f, 0.f);
        for (int i = tid; i < 8 * 65; i += TPB) { sHA[i] = z; sHB[i] = z; }
    }
    __syncthreads();

    const unsigned long long* sA2 = (const unsigned long long*)sHA;
    const unsigned long long* sB2 = (const unsigned long long*)sHB;
    const unsigned* flA = &g_flagA[head << 5];
    const unsigned* flB = &g_flagB[head << 5];

    for (int t = 0; t < T_STEPS; ++t) {
        // ---- loop top: LDG h_A(t-1) into regs (poll done last iter), x prefetch ----
        float4 rA0, rA1;
        {
            int i0 = tid, i1 = tid + 256;
            if (t > 0) {
                const float* hb = out + (size_t)(t - 1) * (BATCH * HID) + hbase;
                rA0 = __ldcg((const float4*)(hb + (i0 >> 6) * HID) + (i0 & 63));
                rA1 = __ldcg((const float4*)(hb + (i1 >> 6) * HID) + (i1 & 63));
            }
        }
        float xA[4], xB[4];
        if (tid < 64) {
            const float* xa = x + (size_t)(t * BATCH + bel) * 4096 + q_u;
            const float* xb = xa + 8 * 4096;
            #pragma unroll
            for (int g = 0; g < 4; ++g) { xA[g] = __ldg(xa + (g << 10)); xB[g] = __ldg(xb + (g << 10)); }
        }

        // ---- GEMM stream B (sHB = h_B(t-1)); hides rA LDG latency ----
        {
            unsigned long long acc[8];
            #pragma unroll
            for (int q = 0; q < 8; ++q) acc[q] = 0ull;
            #pragma unroll
            for (int j = 0; j < 8; ++j) {
                int jj = (j ^ ks) & 7;
                #pragma unroll
                for (int e = 0; e < 2; ++e) {
                    int slot = (bt + 4 * e) * 65 + 8 * ks + jj;
                    ulonglong2 h = *(const ulonglong2*)(sB2 + slot * 2);
                    #pragma unroll
                    for (int i = 0; i < 4; ++i) {
                        ffma2(acc[i * 2 + e], W2[(i * 8 + j) * 2],     h.x);
                        ffma2(acc[i * 2 + e], W2[(i * 8 + j) * 2 + 1], h.y);
                    }
                }
            }
            // reduce-scatter butterfly over ks (lane bits 0-2)
            float v[8];
            #pragma unroll
            for (int q = 0; q < 8; ++q) v[q] = fold2(acc[q]);
            float w0[4];
            #pragma unroll
            for (int k = 0; k < 4; ++k) {
                float send = s0 ? v[k] : v[k + 4];
                float recv = __shfl_xor_sync(0xffffffffu, send, 1);
                w0[k] = (s0 ? v[k + 4] : v[k]) + recv;
            }
            float u0[2];
            #pragma unroll
            for (int k = 0; k < 2; ++k) {
                float send = s1 ? w0[k] : w0[k + 2];
                float recv = __shfl_xor_sync(0xffffffffu, send, 2);
                u0[k] = (s1 ? w0[k + 2] : w0[k]) + recv;
            }
            {
                float send = s2 ? u0[0] : u0[1];
                float recv = __shfl_xor_sync(0xffffffffu, send, 4);
                float z = (s2 ? u0[1] : u0[0]) + recv;
                int q  = 4 * s0 + 2 * s1 + s2;
                sRaw[(4 * wq + (q >> 1)) * RS + bt + 4 * (q & 1)] = z;
            }
        }
        // stage rA -> sHA (sHA free: last read was GEMM_A of prev iter, barriered)
        if (t > 0) {
            int i0 = tid, i1 = tid + 256;
            int b0 = i0 >> 6, f0 = i0 & 63;
            int b1 = i1 >> 6, f1 = i1 & 63;
            sHA[b0 * 65 + (f0 & 56) + ((f0 ^ (f0 >> 3)) & 7)] = rA0;
            sHB[0].w += 0.f; // no-op keep compiler honest (never executed effectfully)
            sHA[b1 * 65 + (f1 & 56) + ((f1 ^ (f1 >> 3)) & 7)] = rA1;
        }
        __syncthreads();   // sRaw(B) + sHA ready

        // ---- elementwise B (warps 0-1) ; warp 2 polls flagB >= t+1 ----
        if (tid < 64) {
            float iraw = sRaw[(     ch) * RS + bel] + xB[0] + bias_g[0];
            float fraw = sRaw[( 8 + ch) * RS + bel] + xB[1] + bias_g[1];
            float zraw = sRaw[(16 + ch) * RS + bel] + xB[2] + bias_g[2];
            float oraw = sRaw[(24 + ch) * RS + bel] + xB[3] + bias_g[3];
            float hn = gate_update(stB, iraw, fraw, zraw, oraw, t);
            __stcg(&out[(size_t)(t * BATCH + 8 + bel) * HID + q_u], hn);
            asm volatile("bar.sync 1, 64;" ::: "memory");
            if (tid == 0) st_rel(&g_flagB[c], (unsigned)(t + 1));
        } else if (wq == 2 && t + 1 < T_STEPS) {
            const unsigned tgt = (unsigned)(t + 1);
            for (;;) {
                unsigned f = ld_acq(&flB[lane]);
                if (__all_sync(0xffffffffu, f >= tgt)) break;
            }
        }
        __syncthreads();   // elemB + pollB done; sHB free

        // ---- LDG h_B(t) into regs; GEMM stream A hides the latency ----
        float4 rB0, rB1;
        {
            int i0 = tid, i1 = tid + 256;
            const float* hb = out + (size_t)t * (BATCH * HID) + 8 * HID + hbase;
            rB0 = __ldcg((const float4*)(hb + (i0 >> 6) * HID) + (i0 & 63));
            rB1 = __ldcg((const float4*)(hb + (i1 >> 6) * HID) + (i1 & 63));
        }
        {
            unsigned long long acc[8];
            #pragma unroll
            for (int q = 0; q < 8; ++q) acc[q] = 0ull;
            #pragma unroll
            for (int j = 0; j < 8; ++j) {
                int jj = (j ^ ks) & 7;
                #pragma unroll
                for (int e = 0; e < 2; ++e) {
                    int slot = (bt + 4 * e) * 65 + 8 * ks + jj;
                    ulonglong2 h = *(const ulonglong2*)(sA2 + slot * 2);
                    #pragma unroll
                    for (int i = 0; i < 4; ++i) {
                        ffma2(acc[i * 2 + e], W2[(i * 8 + j) * 2],     h.x);
                        ffma2(acc[i * 2 + e], W2[(i * 8 + j) * 2 + 1], h.y);
                    }
                }
            }
            float v[8];
            #pragma unroll
            for (int q = 0; q < 8; ++q) v[q] = fold2(acc[q]);
            float w0[4];
            #pragma unroll
            for (int k = 0; k < 4; ++k) {
                float send = s0 ? v[k] : v[k + 4];
                float recv = __shfl_xor_sync(0xffffffffu, send, 1);
                w0[k] = (s0 ? v[k + 4] : v[k]) + recv;
            }
            float u0[2];
            #pragma unroll
            for (int k = 0; k < 2; ++k) {
                float send = s1 ? w0[k] : w0[k + 2];
                float recv = __shfl_xor_sync(0xffffffffu, send, 2);
                u0[k] = (s1 ? w0[k + 2] : w0[k]) + recv;
            }
            {
                float send = s2 ? u0[0] : u0[1];
                float recv = __shfl_xor_sync(0xffffffffu, send, 4);
                float z = (s2 ? u0[1] : u0[0]) + recv;
                int q  = 4 * s0 + 2 * s1 + s2;
                sRaw[(4 * wq + (q >> 1)) * RS + bt + 4 * (q & 1)] = z;
            }
        }
        // stage rB -> sHB
        {
            int i0 = tid, i1 = tid + 256;
            int b0 = i0 >> 6, f0 = i0 & 63;
            int b1 = i1 >> 6, f1 = i1 & 63;
            sHB[b0 * 65 + (f0 & 56) + ((f0 ^ (f0 >> 3)) & 7)] = rB0;
            sHB[b1 * 65 + (f1 & 56) + ((f1 ^ (f1 >> 3)) & 7)] = rB1;
        }
        __syncthreads();   // sRaw(A) + sHB ready

        // ---- elementwise A (warps 0-1) ; warp 2 polls flagA >= t+1 ----
        if (tid < 64) {
            float iraw = sRaw[(     ch) * RS + bel] + xA[0] + bias_g[0];
            float fraw = sRaw[( 8 + ch) * RS + bel] + xA[1] + bias_g[1];
            float zraw = sRaw[(16 + ch) * RS + bel] + xA[2] + bias_g[2];
            float oraw = sRaw[(24 + ch) * RS + bel] + xA[3] + bias_g[3];
            float hn = gate_update(stA, iraw, fraw, zraw, oraw, t);
            __stcg(&out[(size_t)(t * BATCH + bel) * HID + q_u], hn);
            asm volatile("bar.sync 1, 64;" ::: "memory");
            if (tid == 0) st_rel(&g_flagA[c], (unsigned)(t + 1));
        } else if (wq == 2 && t + 1 < T_STEPS) {
            const unsigned tgt = (unsigned)(t + 1);
            for (;;) {
                unsigned f = ld_acq(&flA[lane]);
                if (__all_sync(0xffffffffu, f >= tgt)) break;
            }
        }
        __syncthreads();   // elemA + pollA done; sHA free for next iter's stage
    }

    if (tid < 64) {
        const size_t FS = (size_t)T_STEPS * BATCH * HID;
        const size_t oA = (size_t)bel * HID + q_u;
        const size_t oB = (size_t)(8 + bel) * HID + q_u;
        out[FS + 0 * BATCH * HID + oA] = stA.h;
        out[FS + 1 * BATCH * HID + oA] = stA.c;
        out[FS + 2 * BATCH * HID + oA] = stA.n;
        out[FS + 3 * BATCH * HID + oA] = stA.m;
        out[FS + 0 * BATCH * HID + oB] = stB.h;
        out[FS + 1 * BATCH * HID + oB] = stB.c;
        out[FS + 2 * BATCH * HID + oB] = stB.n;
        out[FS + 3 * BATCH * HID + oB] = stB.m;
    }
}

extern "C" void kernel_launch(void* const* d_in, const int* in_sizes, int n_in,
                              void* d_out, int out_size) {
    const float* x    = (const float*)d_in[0];
    const float* rk   = (const float*)d_in[1];
    const float* bias = (const float*)d_in[2];
    float* out        = (float*)d_out;

    prep_kernel<<<1, NCTA>>>();
    slstm_kernel<<<NCTA, TPB>>>(x, rk, bias, out);
}

// round 12
// speedup vs baseline: 2.2196x; 2.2196x over previous
#include <cuda_runtime.h>
#include <cstdint>

// sLSTM, T=512, B=16, HID=1024, H=4 heads (D=256), G=4 gates.
// R11: 128 CTAs = 4 heads x 4 batch-groups x 8 channel-CTAs; each (head,bg)
// is a CLUSTER of 8. h is exchanged via DSMEM push (st.async + mbarrier
// complete_tx, 4 KB/CTA/step) instead of L2 flags+staging. GEMM = R8's
// verified 4gates x 4batches x 32k tiles, W in registers, f32x2 FMA,
// shfl k-reduction; fast-math gates (R10-verified).

#define T_STEPS 512
#define BATCH   16
#define HID     1024
#define TPB     256
#define SRS     17
#define CLUSTER 8
#define TXB     4096u   // 8 producers x 128 values x 4B per receiver per step

__device__ __forceinline__ void ffma2(unsigned long long &acc,
                                      unsigned long long a,
                                      unsigned long long b) {
    asm("fma.rn.f32x2 %0, %1, %2, %0;" : "+l"(acc) : "l"(a), "l"(b));
}
__device__ __forceinline__ float fold2(unsigned long long a) {
    return __uint_as_float((unsigned)(a & 0xffffffffu)) +
           __uint_as_float((unsigned)(a >> 32));
}
__device__ __forceinline__ uint32_t smem_u32(const void* p) {
    uint32_t a;
    asm("{ .reg .u64 t; cvta.to.shared.u64 t, %1; cvt.u32.u64 %0, t; }"
        : "=r"(a) : "l"(p));
    return a;
}
__device__ __forceinline__ uint32_t mapa_u32(uint32_t a, uint32_t rank) {
    uint32_t d;
    asm("mapa.shared::cluster.u32 %0, %1, %2;" : "=r"(d) : "r"(a), "r"(rank));
    return d;
}
__device__ __forceinline__ void st_async_f32(uint32_t raddr, float v, uint32_t rmbar) {
    asm volatile(
        "st.async.shared::cluster.mbarrier::complete_tx::bytes.b32 [%0], %1, [%2];"
        :: "r"(raddr), "r"(__float_as_uint(v)), "r"(rmbar) : "memory");
}
__device__ __forceinline__ void mbar_init(uint32_t mbar, uint32_t cnt) {
    asm volatile("mbarrier.init.shared.b64 [%0], %1;" :: "r"(mbar), "r"(cnt) : "memory");
}
__device__ __forceinline__ void mbar_expect_tx(uint32_t mbar, uint32_t bytes) {
    asm volatile("mbarrier.arrive.expect_tx.shared.b64 _, [%0], %1;"
                 :: "r"(mbar), "r"(bytes) : "memory");
}
__device__ __forceinline__ void mbar_wait(uint32_t mbar, uint32_t parity) {
    uint32_t done;
    asm volatile(
        "{\n\t.reg .pred p;\n\t"
        "mbarrier.try_wait.parity.acquire.cta.shared::cta.b64 p, [%1], %2;\n\t"
        "selp.b32 %0, 1, 0, p;\n\t}"
        : "=r"(done) : "r"(mbar), "r"(parity) : "memory");
    if (!done) {
        asm volatile(
            "{\n\t.reg .pred P1;\n\t"
            "WL_%=:\n\t"
            "mbarrier.try_wait.parity.acquire.cta.shared::cta.b64 P1, [%0], %1, 0x989680;\n\t"
            "@P1 bra.uni WD_%=;\n\t"
            "bra.uni WL_%=;\n\t"
            "WD_%=:\n\t}"
            :: "r"(mbar), "r"(parity) : "memory");
    }
}

struct St { float h, c, n, m; };

__device__ __forceinline__ float gate_update(St &s, float iraw, float fraw,
                                             float zraw, float oraw, int t) {
    float e   = __expf(-fabsf(fraw));
    float lf  = s.m + (fraw < 0.f ? fraw : 0.f) - __logf(1.f + e);
    float mn  = (t == 0) ? iraw : fmaxf(iraw, lf);   // all(n==0) only at t=0
    float og  = __fdividef(1.f, 1.f + __expf(-oraw));
    float ig  = __expf(iraw - mn);
    float fg  = __expf(lf - mn);
    float t2  = __expf(2.f * zraw);                  // tanh(z) = 1 - 2/(1+e^{2z})
    float th  = 1.f - __fdividef(2.f, t2 + 1.f);
    float cn  = fg * s.c + ig * th;
    float nn  = fg * s.h + ig;                       // reference uses h here
    float hn  = __fdividef(og * cn, nn);
    s.c = cn; s.n = nn; s.m = mn; s.h = hn;
    return hn;
}

__global__ __launch_bounds__(TPB, 1) __cluster_dims__(CLUSTER, 1, 1)
void slstm_kernel(
    const float* __restrict__ x,     // (512, 16, 4096)
    const float* __restrict__ rk,    // (4, 256, 4, 256)
    const float* __restrict__ bias,  // flat 4096
    float* __restrict__ out)         // outs (512,16,1024) ++ final (4,16,1024)
{
    // double-buffered h tile: [buf][4 batches][65 float4], XOR-swizzled
    __shared__ float4 sH[2][4 * 65];
    __shared__ float  sRaw[32 * SRS + 4];
    __shared__ unsigned long long mbar[2];

    const int c     = blockIdx.x;      // c = (head*4 + bg)*8 + cg -> cluster = (head,bg)
    const int head  = c >> 5;
    const int bg    = (c >> 3) & 3;
    const int cg    = c & 7;
    const int dd0   = cg << 5;         // 32 channels
    const int b0    = bg << 2;         // 4 batches
    const int hbase = head << 8;
    const int tid   = threadIdx.x;
    const int wq    = tid >> 5;
    const int lane  = tid & 31;
    const int rq    = lane & 3;        // channel within warp
    const int ks    = lane >> 2;       // k-slice [32ks, 32ks+32)
    const int ch_t  = (wq << 2) + rq;  // GEMM channel (0..31)

    // ---- one-time W gather into registers (R8-verified formula) ----
    float Wf[128];   // [(i*8+j)*4 + e], gate i, d = 32ks + 4j + e
    {
        const int dd  = dd0 + ch_t;
        const int gx  = dd >> 6;
        const int bbs = (dd & 63) << 2;
        #pragma unroll
        for (int i = 0; i < 4; ++i)
            #pragma unroll
            for (int j = 0; j < 8; ++j)
                #pragma unroll
                for (int e = 0; e < 4; ++e) {
                    int d  = 32 * ks + 4 * j + e;
                    int a  = ((d & 63) << 2) + i;
                    int bb = bbs + (d >> 6);
                    Wf[(i * 8 + j) * 4 + e] =
                        __ldg(&rk[((hbase + a) * 4 + gx) * 256 + bb]);
                }
    }
    const unsigned long long* W2 = (const unsigned long long*)Wf;

    // ---- elementwise role: tid<128 owns (channel ch_u, batch b0+bl_u) ----
    const int ch_u = tid >> 2;         // 0..31
    const int bl_u = tid & 3;          // 0..3
    const int q_u  = hbase + dd0 + ch_u;
    float bias_g[4];
    #pragma unroll
    for (int g = 0; g < 4; ++g) bias_g[g] = bias[(g << 10) + q_u];
    St st = {0.f, 0.f, 0.f, 0.f};

    // DSMEM addressing: remote bases for all 8 cluster ranks
    const uint32_t base   = smem_u32(&sH[0][0]);
    const uint32_t mbOff  = smem_u32(&mbar[0]) - base;
    uint32_t rb[CLUSTER];
    #pragma unroll
    for (int r = 0; r < CLUSTER; ++r) rb[r] = mapa_u32(base, (uint32_t)r);

    // this thread's swizzled slot byte offset within a buffer (head-global channel)
    uint32_t slotByte;
    {
        int f4 = (dd0 + ch_u) >> 2;
        int e  = ch_u & 3;
        int sw = (f4 & 56) + ((f4 ^ (f4 >> 3)) & 7);
        slotByte = (uint32_t)((bl_u * 65 + sw) * 16 + e * 4);
    }

    // init: barriers (count=1: the local expect_tx arrival) + zero buf0
    if (tid == 0) { mbar_init(base + mbOff, 1); mbar_init(base + mbOff + 8, 1); }
    {
        float4 z = make_float4(0.f, 0.f, 0.f, 0.f);
        for (int i = tid; i < 4 * 65; i += TPB) sH[0][i] = z;
    }
    __syncthreads();
    asm volatile("barrier.cluster.arrive.aligned;" ::: "memory");
    asm volatile("barrier.cluster.wait.aligned;"   ::: "memory");

    int ph0 = 0, ph1 = 0;
    const unsigned long long* sH2base = (const unsigned long long*)&sH[0][0];

    for (int t = 0; t < T_STEPS; ++t) {
        const int nb = t & 1;

        // x prefetch (independent of h) — issue before the wait
        float xr[4];
        if (tid < 128) {
            const float* xb = x + (size_t)(t * BATCH + b0 + bl_u) * 4096 + q_u;
            #pragma unroll
            for (int g = 0; g < 4; ++g) xr[g] = __ldg(xb + (g << 10));
        }

        if (t > 0) {
            mbar_wait(base + mbOff + nb * 8, nb ? ph1 : ph0);
            if (nb) ph1 ^= 1; else ph0 ^= 1;
        }
        // arm next buffer's barrier (its previous phase completed at step t-1)
        if (tid == 0 && t + 1 < T_STEPS)
            mbar_expect_tx(base + mbOff + ((t + 1) & 1) * 8, TXB);

        // ---- GEMM (R8-verified): 4 gates x 4 batches, k-slice 32ks ----
        const unsigned long long* sB = sH2base + nb * (4 * 65 * 2);
        unsigned long long acc[16];
        #pragma unroll
        for (int q = 0; q < 16; ++q) acc[q] = 0ull;
        #pragma unroll
        for (int j = 0; j < 8; ++j) {
            int jj = (j ^ ks) & 7;
            unsigned long long hlo[4], hhi[4];
            #pragma unroll
            for (int bl = 0; bl < 4; ++bl) {
                int idx = (bl * 65 + (ks << 3) + jj) << 1;
                hlo[bl] = sB[idx];
                hhi[bl] = sB[idx + 1];
            }
            #pragma unroll
            for (int i = 0; i < 4; ++i) {
                unsigned long long wlo = W2[(i * 8 + j) * 2];
                unsigned long long whi = W2[(i * 8 + j) * 2 + 1];
                #pragma unroll
                for (int bl = 0; bl < 4; ++bl) {
                    ffma2(acc[i * 4 + bl], wlo, hlo[bl]);
                    ffma2(acc[i * 4 + bl], whi, hhi[bl]);
                }
            }
        }
        // k-reduction over the 8 ks groups (lane stride 4)
        #pragma unroll
        for (int q = 0; q < 16; ++q) {
            float v = fold2(acc[q]);
            v += __shfl_xor_sync(0xffffffffu, v, 4);
            v += __shfl_xor_sync(0xffffffffu, v, 8);
            v += __shfl_xor_sync(0xffffffffu, v, 16);
            if (ks == 0) sRaw[ch_t * SRS + (q >> 2) * 4 + (q & 3)] = v;
        }
        __syncthreads();

        // ---- elementwise + DSMEM push of h_t to all 8 cluster ranks ----
        if (tid < 128) {
            const float* rw = &sRaw[ch_u * SRS + bl_u];
            float iraw = rw[ 0] + xr[0] + bias_g[0];
            float fraw = rw[ 4] + xr[1] + bias_g[1];
            float zraw = rw[ 8] + xr[2] + bias_g[2];
            float oraw = rw[12] + xr[3] + bias_g[3];
            float hn = gate_update(st, iraw, fraw, zraw, oraw, t);
            __stcg(&out[(size_t)(t * BATCH + b0 + bl_u) * HID + q_u], hn);
            if (t + 1 < T_STEPS) {
                uint32_t doff = (uint32_t)(((t + 1) & 1) * (4 * 65 * 16)) + slotByte;
                uint32_t moff = mbOff + ((t + 1) & 1) * 8;
                #pragma unroll
                for (int r = 0; r < CLUSTER; ++r)
                    st_async_f32(rb[r] + doff, hn, rb[r] + moff);
            }
        }
        // no CTA barrier: next step's wait (which includes our OWN tx) orders
        // the sRaw WAR and the buffer reuse; sends follow the sRaw reads.
    }

    if (tid < 128) {
        const size_t FS = (size_t)T_STEPS * BATCH * HID;
        const size_t o  = (size_t)(b0 + bl_u) * HID + q_u;
        out[FS + 0 * BATCH * HID + o] = st.h;
        out[FS + 1 * BATCH * HID + o] = st.c;
        out[FS + 2 * BATCH * HID + o] = st.n;
        out[FS + 3 * BATCH * HID + o] = st.m;
    }
    // all sends were skipped at t = T-1 -> nothing in flight; exit directly
}

extern "C" void kernel_launch(void* const* d_in, const int* in_sizes, int n_in,
                              void* d_out, int out_size) {
    const float* x    = (const float*)d_in[0];
    const float* rk   = (const float*)d_in[1];
    const float* bias = (const float*)d_in[2];
    float* out        = (float*)d_out;

    slstm_kernel<<<128, TPB>>>(x, rk, bias, out);
}

// round 13
// speedup vs baseline: 2.3346x; 1.0518x over previous
#include <cuda_runtime.h>
#include <cstdint>

// sLSTM, T=512, B=16, HID=1024, H=4 heads (D=256), G=4 gates.
// R13: R11 cluster design, but h exchange = 8x 512B cp.async.bulk (SMEM->SMEM
// cluster) instead of 1024 scattered st.async -> 8 tx updates per mbarrier
// per step instead of 1024. Tile layout rank-major; GEMM k-slice == rank.

#define T_STEPS 512
#define BATCH   16
#define HID     1024
#define TPB     256
#define SRS     17
#define CLUSTER 8
#define TXB     4096u    // 8 copies x 512 B per receiver per step

__device__ __forceinline__ void ffma2(unsigned long long &acc,
                                      unsigned long long a,
                                      unsigned long long b) {
    asm("fma.rn.f32x2 %0, %1, %2, %0;" : "+l"(acc) : "l"(a), "l"(b));
}
__device__ __forceinline__ float fold2(unsigned long long a) {
    return __uint_as_float((unsigned)(a & 0xffffffffu)) +
           __uint_as_float((unsigned)(a >> 32));
}
__device__ __forceinline__ uint32_t smem_u32(const void* p) {
    uint32_t a;
    asm("{ .reg .u64 t; cvta.to.shared.u64 t, %1; cvt.u32.u64 %0, t; }"
        : "=r"(a) : "l"(p));
    return a;
}
__device__ __forceinline__ uint32_t mapa_u32(uint32_t a, uint32_t rank) {
    uint32_t d;
    asm("mapa.shared::cluster.u32 %0, %1, %2;" : "=r"(d) : "r"(a), "r"(rank));
    return d;
}
__device__ __forceinline__ void bulk_copy_s2s(uint32_t dst_cluster, uint32_t src_cta,
                                              uint32_t bytes, uint32_t mbar_cluster) {
    asm volatile(
        "cp.async.bulk.shared::cluster.shared::cta.mbarrier::complete_tx::bytes "
        "[%0], [%1], %2, [%3];"
        :: "r"(dst_cluster), "r"(src_cta), "r"(bytes), "r"(mbar_cluster) : "memory");
}
__device__ __forceinline__ void mbar_init(uint32_t mbar, uint32_t cnt) {
    asm volatile("mbarrier.init.shared.b64 [%0], %1;" :: "r"(mbar), "r"(cnt) : "memory");
}
__device__ __forceinline__ void mbar_expect_tx(uint32_t mbar, uint32_t bytes) {
    asm volatile("mbarrier.arrive.expect_tx.shared.b64 _, [%0], %1;"
                 :: "r"(mbar), "r"(bytes) : "memory");
}
__device__ __forceinline__ void mbar_wait(uint32_t mbar, uint32_t parity) {
    uint32_t done;
    asm volatile(
        "{\n\t.reg .pred p;\n\t"
        "mbarrier.try_wait.parity.acquire.cta.shared::cta.b64 p, [%1], %2;\n\t"
        "selp.b32 %0, 1, 0, p;\n\t}"
        : "=r"(done) : "r"(mbar), "r"(parity) : "memory");
    if (!done) {
        asm volatile(
            "{\n\t.reg .pred P1;\n\t"
            "WL_%=:\n\t"
            "mbarrier.try_wait.parity.acquire.cta.shared::cta.b64 P1, [%0], %1, 0x989680;\n\t"
            "@P1 bra.uni WD_%=;\n\t"
            "bra.uni WL_%=;\n\t"
            "WD_%=:\n\t}"
            :: "r"(mbar), "r"(parity) : "memory");
    }
}
__device__ __forceinline__ void fence_proxy_async_cta() {
    asm volatile("fence.proxy.async.shared::cta;" ::: "memory");
}

struct St { float h, c, n, m; };

__device__ __forceinline__ float gate_update(St &s, float iraw, float fraw,
                                             float zraw, float oraw, int t) {
    float e   = __expf(-fabsf(fraw));
    float lf  = s.m + (fraw < 0.f ? fraw : 0.f) - __logf(1.f + e);
    float mn  = (t == 0) ? iraw : fmaxf(iraw, lf);   // all(n==0) only at t=0
    float og  = __fdividef(1.f, 1.f + __expf(-oraw));
    float ig  = __expf(iraw - mn);
    float fg  = __expf(lf - mn);
    float t2  = __expf(2.f * zraw);                  // tanh(z) = 1 - 2/(1+e^{2z})
    float th  = 1.f - __fdividef(2.f, t2 + 1.f);
    float cn  = fg * s.c + ig * th;
    float nn  = fg * s.h + ig;                       // reference uses h here
    float hn  = __fdividef(og * cn, nn);
    s.c = cn; s.n = nn; s.m = mn; s.h = hn;
    return hn;
}

__global__ __launch_bounds__(TPB, 1) __cluster_dims__(CLUSTER, 1, 1)
void slstm_kernel(
    const float* __restrict__ x,     // (512, 16, 4096)
    const float* __restrict__ rk,    // (4, 256, 4, 256)
    const float* __restrict__ bias,  // flat 4096
    float* __restrict__ out)         // outs (512,16,1024) ++ final (4,16,1024)
{
    // h tile, double-buffered, rank-major: [buf][rank(8)][bl(4)][8 float4]
    __shared__ float4 sT[2][256];
    // staging for outgoing h block: [buf][bl(4)][8 float4] = 512 B each
    __shared__ float4 sStage[2][32];
    __shared__ float  sRaw[32 * SRS + 4];
    __shared__ unsigned long long mbar[2];

    const int c     = blockIdx.x;      // cluster = (head, bg), rank = cg
    const int head  = c >> 5;
    const int bg    = (c >> 3) & 3;
    const int cg    = c & 7;
    const int dd0   = cg << 5;
    const int b0    = bg << 2;
    const int hbase = head << 8;
    const int tid   = threadIdx.x;
    const int wq    = tid >> 5;
    const int lane  = tid & 31;
    const int rq    = lane & 3;        // channel within warp
    const int ks    = lane >> 2;       // k-slice == producer rank
    const int ch_t  = (wq << 2) + rq;  // GEMM channel (0..31)

    // ---- one-time W gather into registers (R8/R11-verified formula) ----
    float Wf[128];   // [(i*8+j)*4 + e], gate i, d = 32ks + 4j + e
    {
        const int dd  = dd0 + ch_t;
        const int gx  = dd >> 6;
        const int bbs = (dd & 63) << 2;
        #pragma unroll
        for (int i = 0; i < 4; ++i)
            #pragma unroll
            for (int j = 0; j < 8; ++j)
                #pragma unroll
                for (int e = 0; e < 4; ++e) {
                    int d  = 32 * ks + 4 * j + e;
                    int a  = ((d & 63) << 2) + i;
                    int bb = bbs + (d >> 6);
                    Wf[(i * 8 + j) * 4 + e] =
                        __ldg(&rk[((hbase + a) * 4 + gx) * 256 + bb]);
                }
    }
    const unsigned long long* W2 = (const unsigned long long*)Wf;

    // ---- elementwise role: tid<128 owns (channel ch_u, batch b0+bl_u) ----
    const int ch_u = tid >> 2;
    const int bl_u = tid & 3;
    const int q_u  = hbase + dd0 + ch_u;
    float bias_g[4];
    #pragma unroll
    for (int g = 0; g < 4; ++g) bias_g[g] = bias[(g << 10) + q_u];
    St st = {0.f, 0.f, 0.f, 0.f};

    // staging float index: f4 slot bl_u*8 + ((ch_u>>2) ^ cg), elem ch_u&3
    const int stageIdx = ((bl_u << 3) + (((ch_u >> 2) ^ cg) & 7)) * 4 + (ch_u & 3);

    const uint32_t tileAddr  = smem_u32(&sT[0][0]);
    const uint32_t stageAddr = smem_u32(&sStage[0][0]);
    const uint32_t mbarAddr  = smem_u32(&mbar[0]);

    // init barriers (count=1: local expect_tx arrival) + zero buf0
    if (tid == 0) { mbar_init(mbarAddr, 1); mbar_init(mbarAddr + 8, 1); }
    {
        float4 z = make_float4(0.f, 0.f, 0.f, 0.f);
        for (int i = tid; i < 256; i += TPB) sT[0][i] = z;
    }
    __syncthreads();
    asm volatile("barrier.cluster.arrive.aligned;" ::: "memory");
    asm volatile("barrier.cluster.wait.aligned;"   ::: "memory");

    int ph0 = 0, ph1 = 0;
    const unsigned long long* sT2 = (const unsigned long long*)&sT[0][0];

    for (int t = 0; t < T_STEPS; ++t) {
        const int nb = t & 1;

        // x prefetch (independent of h) — issue before the wait
        float xr[4];
        if (tid < 128) {
            const float* xb = x + (size_t)(t * BATCH + b0 + bl_u) * 4096 + q_u;
            #pragma unroll
            for (int g = 0; g < 4; ++g) xr[g] = __ldg(xb + (g << 10));
        }

        if (t > 0) {
            mbar_wait(mbarAddr + nb * 8, nb ? ph1 : ph0);
            if (nb) ph1 ^= 1; else ph0 ^= 1;
        }
        if (tid == 0 && t + 1 < T_STEPS)
            mbar_expect_tx(mbarAddr + ((t + 1) & 1) * 8, TXB);

        // ---- GEMM: 4 gates x 4 batches, k-slice = rank ks ----
        const unsigned long long* sB = sT2 + nb * (256 * 2);
        unsigned long long acc[16];
        #pragma unroll
        for (int q = 0; q < 16; ++q) acc[q] = 0ull;
        #pragma unroll
        for (int j = 0; j < 8; ++j) {
            int jj = (j ^ ks) & 7;
            unsigned long long hlo[4], hhi[4];
            #pragma unroll
            for (int bl = 0; bl < 4; ++bl) {
                int idx = ((ks << 5) + (bl << 3) + jj) << 1;   // f4 slot * 2
                hlo[bl] = sB[idx];
                hhi[bl] = sB[idx + 1];
            }
            #pragma unroll
            for (int i = 0; i < 4; ++i) {
                unsigned long long wlo = W2[(i * 8 + j) * 2];
                unsigned long long whi = W2[(i * 8 + j) * 2 + 1];
                #pragma unroll
                for (int bl = 0; bl < 4; ++bl) {
                    ffma2(acc[i * 4 + bl], wlo, hlo[bl]);
                    ffma2(acc[i * 4 + bl], whi, hhi[bl]);
                }
            }
        }
        // k-reduction over the 8 ks groups (lane stride 4)
        #pragma unroll
        for (int q = 0; q < 16; ++q) {
            float v = fold2(acc[q]);
            v += __shfl_xor_sync(0xffffffffu, v, 4);
            v += __shfl_xor_sync(0xffffffffu, v, 8);
            v += __shfl_xor_sync(0xffffffffu, v, 16);
            if (ks == 0) sRaw[ch_t * SRS + (q >> 2) * 4 + (q & 3)] = v;
        }
        __syncthreads();

        // ---- elementwise; h_t -> out + local staging ----
        if (tid < 128) {
            const float* rw = &sRaw[ch_u * SRS + bl_u];
            float iraw = rw[ 0] + xr[0] + bias_g[0];
            float fraw = rw[ 4] + xr[1] + bias_g[1];
            float zraw = rw[ 8] + xr[2] + bias_g[2];
            float oraw = rw[12] + xr[3] + bias_g[3];
            float hn = gate_update(st, iraw, fraw, zraw, oraw, t);
            __stcg(&out[(size_t)(t * BATCH + b0 + bl_u) * HID + q_u], hn);
            ((float*)&sStage[nb][0])[stageIdx] = hn;
            // writers-only barrier, then one thread bulk-copies to all 8 ranks
            asm volatile("bar.sync 1, 128;" ::: "memory");
            if (tid == 0 && t + 1 < T_STEPS) {
                fence_proxy_async_cta();
                const uint32_t src   = stageAddr + (uint32_t)nb * 512u;
                const uint32_t dOff  = (uint32_t)(((t + 1) & 1) * 4096 + cg * 512);
                const uint32_t mOff  = (uint32_t)(((t + 1) & 1) * 8);
                #pragma unroll
                for (int r = 0; r < CLUSTER; ++r) {
                    uint32_t dst = mapa_u32(tileAddr, (uint32_t)r) + dOff;
                    uint32_t mb  = mapa_u32(mbarAddr, (uint32_t)r) + mOff;
                    bulk_copy_s2s(dst, src, 512u, mb);
                }
            }
        }
        // no CTA-wide trailing barrier: next wait orders tile/sRaw reuse
        // (our own incoming copy is part of the 4096-byte expectation).
    }

    if (tid < 128) {
        const size_t FS = (size_t)T_STEPS * BATCH * HID;
        const size_t o  = (size_t)(b0 + bl_u) * HID + q_u;
        out[FS + 0 * BATCH * HID + o] = st.h;
        out[FS + 1 * BATCH * HID + o] = st.c;
        out[FS + 2 * BATCH * HID + o] = st.n;
        out[FS + 3 * BATCH * HID + o] = st.m;
    }
    // last-step pushes are skipped -> no in-flight transfers at exit
}

extern "C" void kernel_launch(void* const* d_in, const int* in_sizes, int n_in,
                              void* d_out, int out_size) {
    const float* x    = (const float*)d_in[0];
    const float* rk   = (const float*)d_in[1];
    const float* bias = (const float*)d_in[2];
    float* out        = (float*)d_out;

    slstm_kernel<<<128, TPB>>>(x, rk, bias, out);
}